// round 10
// baseline (speedup 1.0000x reference)
#include <cuda_runtime.h>
#include <math.h>
#include <stdint.h>

// ----------------------------------------------------------------------------
// Problem constants
//   T=32, B=32, TB=1024, NA=5, HID=256, FEAT=512, IN_DIM=517 (pad 544), FLAT=3136
// Output layout (22528 floats): logits[1024*5] | v[1024] | hT[32*256] | cT[32*256]
// ----------------------------------------------------------------------------

#define TBn 1024
#define KPAD 544    // padded IN_DIM for tf32 GEMM (multiple of 32)

typedef unsigned long long ull;

// Scratch (device globals; no allocation allowed)
__device__ float g_x1[TBn * 32 * 20 * 20];   // conv1 out
__device__ float g_x2[TBn * 64 * 9 * 9];     // conv2 out
__device__ float g_x3[TBn * 3136];           // conv3 out (flatten, C,H,W)
__device__ float g_xs[TBn * KPAD];           // feat || one-hot || zero pad
__device__ float g_pre[TBn * 1024];          // x @ W_ih^T + b_ih + b_hh
__device__ float g_whhT[256 * 1024];         // W_hh transposed: [k][4*HID]
__device__ float g_wihp[1024 * KPAD];        // W_ih zero-padded to KPAD
__device__ float g_bsum[1024];               // b_ih + b_hh
__device__ float g_wp1T[256 * 64];           // Wp1 transposed [k][64]
__device__ float g_wv1T[256 * 64];           // Wv1 transposed [k][64]
__device__ float g_hs[TBn * 256];            // all h outputs
// Pre-packed conv weights, transposed to [k][oc].
__device__ float g_w1p[192 * 32];            // conv1 W
__device__ float g_w2p[512 * 64];            // conv2 W
__device__ float g_w3p[576 * 64];            // conv3 W

__device__ __forceinline__ float sigmoidf(float x) { return 1.0f / (1.0f + expf(-x)); }

__device__ __forceinline__ unsigned f2tf(float f) {
    unsigned u;
    asm("cvt.rna.tf32.f32 %0, %1;" : "=r"(u) : "f"(f));
    return u;
}

// ---- packed f32x2 helpers (Blackwell FFMA2) ----
__device__ __forceinline__ ull pk2(float x, float y) {
    ull r;
    asm("mov.b64 %0, {%1, %2};" : "=l"(r) : "f"(x), "f"(y));
    return r;
}
__device__ __forceinline__ float2 upk2(ull v) {
    float2 f;
    asm("mov.b64 {%0, %1}, %2;" : "=f"(f.x), "=f"(f.y) : "l"(v));
    return f;
}
__device__ __forceinline__ void ffma2(ull& d, ull a, ull b) {
    asm("fma.rn.f32x2 %0, %1, %2, %3;" : "=l"(d) : "l"(a), "l"(b), "l"(d));
}

// ---- cluster / DSMEM helpers ----
__device__ __forceinline__ uint32_t smem_u32(const void* p) {
    uint32_t a;
    asm("{ .reg .u64 t; cvta.to.shared.u64 t, %1; cvt.u32.u64 %0, t; }"
        : "=r"(a) : "l"(p));
    return a;
}
__device__ __forceinline__ uint32_t mapa_rank(uint32_t saddr, uint32_t rank) {
    uint32_t r;
    asm("mapa.shared::cluster.u32 %0, %1, %2;" : "=r"(r) : "r"(saddr), "r"(rank));
    return r;
}
__device__ __forceinline__ void st_cluster_f32(uint32_t addr, float v) {
    asm volatile("st.shared::cluster.f32 [%0], %1;" :: "r"(addr), "f"(v) : "memory");
}
#define CLUSTER_SYNC() do { \
    asm volatile("barrier.cluster.arrive.aligned;" ::: "memory"); \
    asm volatile("barrier.cluster.wait.aligned;" ::: "memory"); \
} while (0)

// ----------------------------------------------------------------------------
// prep
// ----------------------------------------------------------------------------
__global__ void prep_kernel(const float* __restrict__ W_hh,
                            const float* __restrict__ b_ih,
                            const float* __restrict__ b_hh,
                            const float* __restrict__ Wp1,
                            const float* __restrict__ Wv1,
                            const float* __restrict__ W1,
                            const float* __restrict__ W2,
                            const float* __restrict__ W3,
                            const float* __restrict__ W_ih) {
    int idx = blockIdx.x * blockDim.x + threadIdx.x;
    if (idx < 262144) {
        int j = idx >> 8, k = idx & 255;
        g_whhT[k * 1024 + j] = W_hh[idx];
    }
    if (idx < 16384) {
        int j = idx >> 8, k = idx & 255;
        g_wp1T[k * 64 + j] = Wp1[idx];
        g_wv1T[k * 64 + j] = Wv1[idx];
    }
    if (idx < 1024) g_bsum[idx] = b_ih[idx] + b_hh[idx];
    if (idx < 6144) {
        int oc = idx / 192, k = idx % 192;
        g_w1p[k * 32 + oc] = W1[idx];
    }
    if (idx < 32768) {
        int oc = idx >> 9, k = idx & 511;
        g_w2p[k * 64 + oc] = W2[idx];
    }
    if (idx < 36864) {
        int oc = idx / 576, k = idx % 576;
        g_w3p[k * 64 + oc] = W3[idx];
    }
    if (idx < 1024 * KPAD) {
        int row = idx / KPAD, col = idx % KPAD;
        g_wihp[idx] = (col < 517) ? W_ih[row * 517 + col] : 0.0f;
    }
}

// ----------------------------------------------------------------------------
// one-hot columns of xs (cols 512..516) + zero pad (517..543)
// ----------------------------------------------------------------------------
__global__ void onehot_kernel(const int* __restrict__ la) {
    int r = blockIdx.x * blockDim.x + threadIdx.x;
    if (r < TBn) {
        int a = la[r];
        float* p = g_xs + r * KPAD + 512;
#pragma unroll
        for (int j = 0; j < 5; j++) p[j] = (j == a) ? 1.0f : 0.0f;
#pragma unroll
        for (int j = 5; j < 32; j++) p[j] = 0.0f;
    }
}

// ----------------------------------------------------------------------------
// conv1: in (TB,3,84,84)/255, W (32,3,8,8) stride4 -> (TB,32,20,20) relu
// FFMA2: 8 oc accumulators packed as 4 f32x2 per pixel.
// ----------------------------------------------------------------------------
__global__ void __launch_bounds__(640, 1)
conv1_kernel(const float* __restrict__ img, const float* __restrict__ b1) {
    extern __shared__ float sm[];            // 2 * 21168 floats
    int tid = threadIdx.x;
    {
        const float4* g4 = reinterpret_cast<const float4*>(img + blockIdx.x * 2 * 21168);
        float4* s4 = reinterpret_cast<float4*>(sm);
        for (int i = tid; i < 10584; i += 640) {
            float4 v = g4[i];
            v.x *= (1.0f / 255.0f); v.y *= (1.0f / 255.0f);
            v.z *= (1.0f / 255.0f); v.w *= (1.0f / 255.0f);
            s4[i] = v;
        }
    }
    __syncthreads();

    int im = tid / 320, r = tid % 320;
    int oy = r >> 4, q = (r >> 2) & 3, ocg = r & 3;
    const float* ims = sm + im * 21168;
    const float4* w4 = reinterpret_cast<const float4*>(g_w1p);

    ull acc[5][4];
#pragma unroll
    for (int p = 0; p < 5; p++)
#pragma unroll
        for (int c = 0; c < 4; c++) acc[p][c] = 0ULL;

    for (int ic = 0; ic < 3; ic++) {
        for (int ky = 0; ky < 8; ky++) {
            const float* row = ims + ic * 7056 + (oy * 4 + ky) * 84 + q * 20;
            float rr[24];
#pragma unroll
            for (int v = 0; v < 6; v++) {
                float4 t = *reinterpret_cast<const float4*>(row + v * 4);
                rr[v * 4 + 0] = t.x; rr[v * 4 + 1] = t.y;
                rr[v * 4 + 2] = t.z; rr[v * 4 + 3] = t.w;
            }
            int kbase = (ic * 8 + ky) * 8;
#pragma unroll
            for (int kx = 0; kx < 8; kx++) {
                int k = kbase + kx;
                const ulonglong2* wp = reinterpret_cast<const ulonglong2*>(&w4[k * 8 + ocg * 2]);
                ulonglong2 wa = __ldg(wp);
                ulonglong2 wb = __ldg(wp + 1);
#pragma unroll
                for (int p = 0; p < 5; p++) {
                    float v = rr[p * 4 + kx];
                    ull vv = pk2(v, v);
                    ffma2(acc[p][0], vv, wa.x);
                    ffma2(acc[p][1], vv, wa.y);
                    ffma2(acc[p][2], vv, wb.x);
                    ffma2(acc[p][3], vv, wb.y);
                }
            }
        }
    }
    int n = blockIdx.x * 2 + im;
    float* o = g_x1 + n * 12800;
#pragma unroll
    for (int c = 0; c < 4; c++) {
        int oc0 = ocg * 8 + c * 2;
        float bb0 = __ldg(&b1[oc0]);
        float bb1 = __ldg(&b1[oc0 + 1]);
        float* op0 = o + oc0 * 400 + oy * 20 + q * 5;
        float* op1 = op0 + 400;
#pragma unroll
        for (int p = 0; p < 5; p++) {
            float2 f = upk2(acc[p][c]);
            op0[p] = fmaxf(f.x + bb0, 0.0f);
            op1[p] = fmaxf(f.y + bb1, 0.0f);
        }
    }
}

// ----------------------------------------------------------------------------
// conv2: (TB,32,20,20) * W(64,32,4,4) s2 -> (TB,64,9,9) relu  (FFMA2)
// ----------------------------------------------------------------------------
__global__ void __launch_bounds__(288, 1)
conv2_kernel(const float* __restrict__ b2) {
    extern __shared__ float sm[];            // 4 * 12800 floats
    int tid = threadIdx.x;
    {
        const float4* g4 = reinterpret_cast<const float4*>(g_x1 + blockIdx.x * 4 * 12800);
        float4* s4 = reinterpret_cast<float4*>(sm);
        for (int i = tid; i < 12800; i += 288) s4[i] = g4[i];
    }
    __syncthreads();

    int im = tid / 72, r = tid % 72;
    int oy = r >> 3, ocg = r & 7;
    const float* ims = sm + im * 12800;
    const float4* w4 = reinterpret_cast<const float4*>(g_w2p);

    ull acc[9][4];
#pragma unroll
    for (int p = 0; p < 9; p++)
#pragma unroll
        for (int c = 0; c < 4; c++) acc[p][c] = 0ULL;

    for (int ic = 0; ic < 32; ic++) {
#pragma unroll
        for (int ky = 0; ky < 4; ky++) {
            const float* row = ims + ic * 400 + (oy * 2 + ky) * 20;
            float rr[20];
#pragma unroll
            for (int v = 0; v < 5; v++) {
                float4 t = *reinterpret_cast<const float4*>(row + v * 4);
                rr[v * 4 + 0] = t.x; rr[v * 4 + 1] = t.y;
                rr[v * 4 + 2] = t.z; rr[v * 4 + 3] = t.w;
            }
            int kbase = (ic * 4 + ky) * 4;
#pragma unroll
            for (int kx = 0; kx < 4; kx++) {
                int k = kbase + kx;
                const ulonglong2* wp = reinterpret_cast<const ulonglong2*>(&w4[k * 16 + ocg * 2]);
                ulonglong2 wa = __ldg(wp);
                ulonglong2 wb = __ldg(wp + 1);
#pragma unroll
                for (int p = 0; p < 9; p++) {
                    float v = rr[p * 2 + kx];
                    ull vv = pk2(v, v);
                    ffma2(acc[p][0], vv, wa.x);
                    ffma2(acc[p][1], vv, wa.y);
                    ffma2(acc[p][2], vv, wb.x);
                    ffma2(acc[p][3], vv, wb.y);
                }
            }
        }
    }
    int n = blockIdx.x * 4 + im;
    float* o = g_x2 + n * 5184;
#pragma unroll
    for (int c = 0; c < 4; c++) {
        int oc0 = ocg * 8 + c * 2;
        float bb0 = __ldg(&b2[oc0]);
        float bb1 = __ldg(&b2[oc0 + 1]);
        float* op0 = o + oc0 * 81 + oy * 9;
        float* op1 = op0 + 81;
#pragma unroll
        for (int p = 0; p < 9; p++) {
            float2 f = upk2(acc[p][c]);
            op0[p] = fmaxf(f.x + bb0, 0.0f);
            op1[p] = fmaxf(f.y + bb1, 0.0f);
        }
    }
}

// ----------------------------------------------------------------------------
// conv3: (TB,64,9,9) * W(64,64,3,3) s1 -> (TB,64,7,7) relu -> flatten (FFMA2)
// ----------------------------------------------------------------------------
__global__ void __launch_bounds__(448, 1)
conv3_kernel(const float* __restrict__ b3) {
    extern __shared__ float sm[];            // 8 * 5184 floats
    int tid = threadIdx.x;
    {
        const float4* g4 = reinterpret_cast<const float4*>(g_x2 + blockIdx.x * 8 * 5184);
        float4* s4 = reinterpret_cast<float4*>(sm);
        for (int i = tid; i < 10368; i += 448) s4[i] = g4[i];
    }
    __syncthreads();

    int im = tid / 56, r = tid % 56;
    int oy = r >> 3, ocg = r & 7;
    const float* ims = sm + im * 5184;
    const float4* w4 = reinterpret_cast<const float4*>(g_w3p);

    ull acc[7][4];
#pragma unroll
    for (int p = 0; p < 7; p++)
#pragma unroll
        for (int c = 0; c < 4; c++) acc[p][c] = 0ULL;

    for (int ic = 0; ic < 64; ic++) {
#pragma unroll
        for (int ky = 0; ky < 3; ky++) {
            const float* row = ims + ic * 81 + (oy + ky) * 9;
            ull rr2[9];
#pragma unroll
            for (int v = 0; v < 9; v++) {
                float t = row[v];
                rr2[v] = pk2(t, t);
            }
            int kbase = (ic * 3 + ky) * 3;
#pragma unroll
            for (int kx = 0; kx < 3; kx++) {
                int k = kbase + kx;
                const ulonglong2* wp = reinterpret_cast<const ulonglong2*>(&w4[k * 16 + ocg * 2]);
                ulonglong2 wa = __ldg(wp);
                ulonglong2 wb = __ldg(wp + 1);
#pragma unroll
                for (int p = 0; p < 7; p++) {
                    ull vv = rr2[p + kx];
                    ffma2(acc[p][0], vv, wa.x);
                    ffma2(acc[p][1], vv, wa.y);
                    ffma2(acc[p][2], vv, wb.x);
                    ffma2(acc[p][3], vv, wb.y);
                }
            }
        }
    }
    int n = blockIdx.x * 8 + im;
    float* o = g_x3 + n * 3136;
#pragma unroll
    for (int c = 0; c < 4; c++) {
        int oc0 = ocg * 8 + c * 2;
        float bb0 = __ldg(&b3[oc0]);
        float bb1 = __ldg(&b3[oc0 + 1]);
        float* op0 = o + oc0 * 49 + oy * 7;
        float* op1 = op0 + 49;
#pragma unroll
        for (int p = 0; p < 7; p++) {
            float2 f = upk2(acc[p][c]);
            op0[p] = fmaxf(f.x + bb0, 0.0f);
            op1[p] = fmaxf(f.y + bb1, 0.0f);
        }
    }
}

// ----------------------------------------------------------------------------
// tf32 tensor-core GEMM: C[M x N] = act(A[M x K] * B[N x K]^T + bias)
// ----------------------------------------------------------------------------
__device__ __forceinline__ void mma_tf32(float* c, const unsigned* a, const unsigned* b) {
    asm volatile(
        "mma.sync.aligned.m16n8k8.row.col.f32.tf32.tf32.f32 "
        "{%0,%1,%2,%3}, {%4,%5,%6,%7}, {%8,%9}, {%0,%1,%2,%3};\n"
        : "+f"(c[0]), "+f"(c[1]), "+f"(c[2]), "+f"(c[3])
        : "r"(a[0]), "r"(a[1]), "r"(a[2]), "r"(a[3]), "r"(b[0]), "r"(b[1]));
}

__device__ __forceinline__ void gemm_tf32(const float* __restrict__ A, int lda,
                                          const float* __restrict__ B, int ldb,
                                          const float* __restrict__ bias,
                                          float* __restrict__ C, int ldc,
                                          int K, bool relu) {
    __shared__ unsigned As[2][64][36];
    __shared__ unsigned Bs[2][64][36];
    int tid = threadIdx.x, lane = tid & 31, warp = tid >> 5;
    int bm = blockIdx.y * 64, bn = blockIdx.x * 64;
    int wm = (warp & 1) << 5, wn = (warp >> 1) << 5;

    float c[2][4][4];
#pragma unroll
    for (int mt = 0; mt < 2; mt++)
#pragma unroll
        for (int nt = 0; nt < 4; nt++)
#pragma unroll
            for (int i = 0; i < 4; i++) c[mt][nt][i] = 0.0f;

    int ntiles = K >> 5;
    float4 pa[4], pb[4];

#pragma unroll
    for (int i = 0; i < 4; i++) {
        int idx = tid + (i << 7);
        int row = idx >> 3, c4 = (idx & 7) << 2;
        pa[i] = *reinterpret_cast<const float4*>(A + (bm + row) * lda + c4);
        pb[i] = *reinterpret_cast<const float4*>(B + (bn + row) * ldb + c4);
    }
#pragma unroll
    for (int i = 0; i < 4; i++) {
        int idx = tid + (i << 7);
        int row = idx >> 3, c4 = (idx & 7) << 2;
        uint4 ta = {f2tf(pa[i].x), f2tf(pa[i].y), f2tf(pa[i].z), f2tf(pa[i].w)};
        uint4 tb = {f2tf(pb[i].x), f2tf(pb[i].y), f2tf(pb[i].z), f2tf(pb[i].w)};
        *reinterpret_cast<uint4*>(&As[0][row][c4]) = ta;
        *reinterpret_cast<uint4*>(&Bs[0][row][c4]) = tb;
    }
    __syncthreads();

    for (int t = 0; t < ntiles; t++) {
        int buf = t & 1;
        if (t + 1 < ntiles) {
            int k0 = (t + 1) << 5;
#pragma unroll
            for (int i = 0; i < 4; i++) {
                int idx = tid + (i << 7);
                int row = idx >> 3, c4 = (idx & 7) << 2;
                pa[i] = *reinterpret_cast<const float4*>(A + (bm + row) * lda + k0 + c4);
                pb[i] = *reinterpret_cast<const float4*>(B + (bn + row) * ldb + k0 + c4);
            }
        }
        int r = lane >> 2, q = lane & 3;
#pragma unroll
        for (int ks = 0; ks < 4; ks++) {
            unsigned a[2][4], b[4][2];
            int kc = ks << 3;
#pragma unroll
            for (int mt = 0; mt < 2; mt++) {
                int mr = wm + (mt << 4) + r;
                a[mt][0] = As[buf][mr][kc + q];
                a[mt][1] = As[buf][mr + 8][kc + q];
                a[mt][2] = As[buf][mr][kc + q + 4];
                a[mt][3] = As[buf][mr + 8][kc + q + 4];
            }
#pragma unroll
            for (int nt = 0; nt < 4; nt++) {
                int nr = wn + (nt << 3) + r;
                b[nt][0] = Bs[buf][nr][kc + q];
                b[nt][1] = Bs[buf][nr][kc + q + 4];
            }
#pragma unroll
            for (int mt = 0; mt < 2; mt++)
#pragma unroll
                for (int nt = 0; nt < 4; nt++)
                    mma_tf32(c[mt][nt], a[mt], b[nt]);
        }
        if (t + 1 < ntiles) {
            int nbuf = buf ^ 1;
#pragma unroll
            for (int i = 0; i < 4; i++) {
                int idx = tid + (i << 7);
                int row = idx >> 3, c4 = (idx & 7) << 2;
                uint4 ta = {f2tf(pa[i].x), f2tf(pa[i].y), f2tf(pa[i].z), f2tf(pa[i].w)};
                uint4 tb = {f2tf(pb[i].x), f2tf(pb[i].y), f2tf(pb[i].z), f2tf(pb[i].w)};
                *reinterpret_cast<uint4*>(&As[nbuf][row][c4]) = ta;
                *reinterpret_cast<uint4*>(&Bs[nbuf][row][c4]) = tb;
            }
            __syncthreads();
        }
    }

#pragma unroll
    for (int mt = 0; mt < 2; mt++) {
#pragma unroll
        for (int nt = 0; nt < 4; nt++) {
            int row = bm + wm + (mt << 4) + (lane >> 2);
            int col = bn + wn + (nt << 3) + ((lane & 3) << 1);
            float b0 = bias[col], b1 = bias[col + 1];
            float v0 = c[mt][nt][0] + b0;
            float v1 = c[mt][nt][1] + b1;
            float v2 = c[mt][nt][2] + b0;
            float v3 = c[mt][nt][3] + b1;
            if (relu) {
                v0 = fmaxf(v0, 0.0f); v1 = fmaxf(v1, 0.0f);
                v2 = fmaxf(v2, 0.0f); v3 = fmaxf(v3, 0.0f);
            }
            C[row * ldc + col] = v0;
            C[row * ldc + col + 1] = v1;
            C[(row + 8) * ldc + col] = v2;
            C[(row + 8) * ldc + col + 1] = v3;
        }
    }
}

__global__ void __launch_bounds__(128)
gemm_fc_kernel(const float* __restrict__ Wfc, const float* __restrict__ bfc) {
    gemm_tf32(g_x3, 3136, Wfc, 3136, bfc, g_xs, KPAD, 3136, true);
}

__global__ void __launch_bounds__(128)
gemm_pre_kernel() {
    gemm_tf32(g_xs, KPAD, g_wihp, KPAD, g_bsum, g_pre, 1024, KPAD, false);
}

// ----------------------------------------------------------------------------
// LSTM: 4 clusters x 8 CTAs, W_hh slice SMEM-resident, DSMEM gate exchange.
// Inner product uses FFMA2 (2 packed MACs / instr).
// ----------------------------------------------------------------------------
__global__ void __launch_bounds__(256, 1) __cluster_dims__(8, 1, 1)
lstm_kernel(const float* __restrict__ done,
            const float* __restrict__ h0,
            const float* __restrict__ c0,
            float* __restrict__ hT,
            float* __restrict__ cT) {
    extern __shared__ float sm[];
    float* wsl = sm;                    // 256*128 = 32768 floats (weight slice)
    float* h_s = sm + 32768;            // 8*260 = 2080 floats (padded h, full copy)
    float* gbuf = h_s + 2080;           // 4*8*32 = 1024 floats (owned gate values)
    float* m_s = gbuf + 1024;           // 8 floats (masks)

    int tid = threadIdx.x;
    unsigned rank;
    asm("mov.u32 %0, %%cluster_ctarank;" : "=r"(rank));
    int cl = blockIdx.x >> 3;
    int bbase = cl * 8;

    {
        const float* src = g_whhT + 128 * (int)rank;
        for (int i = tid; i < 8192; i += 256) {
            int k = i >> 5, j4 = (i & 31) << 2;
            *reinterpret_cast<float4*>(&wsl[k * 128 + j4]) =
                *reinterpret_cast<const float4*>(&src[k * 1024 + j4]);
        }
    }
    for (int i = tid; i < 2048; i += 256) {
        int b = i >> 8, k = i & 255;
        h_s[b * 260 + k] = h0[(bbase + b) * 256 + k];
    }
    int ob = tid >> 5, os = tid & 31;
    int ou = 32 * (int)rank + os;
    float c_reg = c0[(bbase + ob) * 256 + ou];
    float hn = 0.0f;

    int b = tid & 7, jg = tid >> 3;
    int jbase = 4 * jg;
    int gt = (int)rank >> 1;
    int ubase = ((128 * (int)rank) & 255) + jbase;
    uint32_t owner = (uint32_t)(ubase >> 5);
    uint32_t gbuf_a = smem_u32(gbuf);
    uint32_t h_a = smem_u32(h_s);
    uint32_t peer_gbuf = mapa_rank(gbuf_a, owner);
    uint32_t goff = (uint32_t)(((gt * 8 + b) * 32 + (ubase & 31)) * 4);
    uint32_t hpeer[8];
#pragma unroll
    for (int p = 0; p < 8; p++) hpeer[p] = mapa_rank(h_a, (uint32_t)p);
    uint32_t hoff = (uint32_t)((ob * 260 + ou) * 4);

    __syncthreads();
    CLUSTER_SYNC();

    for (int t = 0; t < 32; t++) {
        if (tid < 8) m_s[tid] = 1.0f - __ldg(&done[t * 32 + bbase + tid]);
        __syncthreads();
        for (int i = tid; i < 2048; i += 256) {
            int bb = i >> 8, k = i & 255;
            h_s[bb * 260 + k] *= m_s[bb];
        }
        c_reg *= m_s[ob];
        __syncthreads();

        int row = (t << 5) + bbase + b;
        float4 a = *reinterpret_cast<const float4*>(
            g_pre + row * 1024 + 128 * (int)rank + jbase);
        ull a01 = pk2(a.x, a.y), a23 = pk2(a.z, a.w);
        const float* hb = h_s + b * 260;
#pragma unroll 8
        for (int k = 0; k < 256; k++) {
            float hv = hb[k];
            ull vv = pk2(hv, hv);
            ulonglong2 w = *reinterpret_cast<const ulonglong2*>(&wsl[k * 128 + jbase]);
            ffma2(a01, vv, w.x);
            ffma2(a23, vv, w.y);
        }
        float2 f01 = upk2(a01), f23 = upk2(a23);
        st_cluster_f32(peer_gbuf + goff, f01.x);
        st_cluster_f32(peer_gbuf + goff + 4, f01.y);
        st_cluster_f32(peer_gbuf + goff + 8, f23.x);
        st_cluster_f32(peer_gbuf + goff + 12, f23.y);
        CLUSTER_SYNC();

        {
            float gi = sigmoidf(gbuf[(0 * 8 + ob) * 32 + os]);
            float gf = sigmoidf(gbuf[(1 * 8 + ob) * 32 + os]);
            float gg = tanhf(gbuf[(2 * 8 + ob) * 32 + os]);
            float go = sigmoidf(gbuf[(3 * 8 + ob) * 32 + os]);
            c_reg = gf * c_reg + gi * gg;
            hn = go * tanhf(c_reg);
            g_hs[((t << 5) + bbase + ob) * 256 + ou] = hn;
#pragma unroll
            for (int p = 0; p < 8; p++) st_cluster_f32(hpeer[p] + hoff, hn);
        }
        CLUSTER_SYNC();
    }
    hT[(bbase + ob) * 256 + ou] = hn;
    cT[(bbase + ob) * 256 + ou] = c_reg;
}

// ----------------------------------------------------------------------------
// Heads: 8 rows per block; weights loaded once per k, 8 FMAs each.
// ----------------------------------------------------------------------------
__global__ void __launch_bounds__(128)
heads_kernel(const float* __restrict__ bp1,
             const float* __restrict__ Wp2,
             const float* __restrict__ bp2,
             const float* __restrict__ bv1,
             const float* __restrict__ Wv2,
             const float* __restrict__ bv2,
             float* __restrict__ logits,
             float* __restrict__ vout) {
    __shared__ float h_s[8][256];
    __shared__ float hp[8][64];
    __shared__ float hv[8][64];
    int r0 = blockIdx.x * 8, t = threadIdx.x;
    {
        const float4* g4 = reinterpret_cast<const float4*>(g_hs + r0 * 256);
        float4* s4 = reinterpret_cast<float4*>(&h_s[0][0]);
        for (int i = t; i < 512; i += 128) s4[i] = g4[i];
    }
    __syncthreads();

    if (t < 64) {
        float s[8];
#pragma unroll
        for (int r = 0; r < 8; r++) s[r] = bp1[t];
#pragma unroll 4
        for (int k = 0; k < 256; k++) {
            float w = __ldg(&g_wp1T[k * 64 + t]);
#pragma unroll
            for (int r = 0; r < 8; r++) s[r] = fmaf(h_s[r][k], w, s[r]);
        }
#pragma unroll
        for (int r = 0; r < 8; r++) hp[r][t] = tanhf(s[r]);
    } else {
        int j = t - 64;
        float s[8];
#pragma unroll
        for (int r = 0; r < 8; r++) s[r] = bv1[j];
#pragma unroll 4
        for (int k = 0; k < 256; k++) {
            float w = __ldg(&g_wv1T[k * 64 + j]);
#pragma unroll
            for (int r = 0; r < 8; r++) s[r] = fmaf(h_s[r][k], w, s[r]);
        }
#pragma unroll
        for (int r = 0; r < 8; r++) hv[r][j] = tanhf(s[r]);
    }
    __syncthreads();

    if (t < 40) {
        int r = t / 5, a = t % 5;
        float s = bp2[a];
#pragma unroll
        for (int k = 0; k < 64; k++) s = fmaf(hp[r][k], Wp2[a * 64 + k], s);
        logits[(r0 + r) * 5 + a] = s;
    }
    if (t >= 64 && t < 72) {
        int r = t - 64;
        float s = bv2[0];
#pragma unroll
        for (int k = 0; k < 64; k++) s = fmaf(hv[r][k], Wv2[k], s);
        vout[r0 + r] = s;
    }
}

// ----------------------------------------------------------------------------
// Launch
// ----------------------------------------------------------------------------
extern "C" void kernel_launch(void* const* d_in, const int* in_sizes, int n_in,
                              void* d_out, int out_size) {
    const float* image = (const float*)d_in[0];
    const int* la = (const int*)d_in[1];
    const float* done = (const float*)d_in[2];
    const float* h0 = (const float*)d_in[3];
    const float* c0 = (const float*)d_in[4];
    const float* W1 = (const float*)d_in[5];
    const float* b1 = (const float*)d_in[6];
    const float* W2 = (const float*)d_in[7];
    const float* b2 = (const float*)d_in[8];
    const float* W3 = (const float*)d_in[9];
    const float* b3 = (const float*)d_in[10];
    const float* Wfc = (const float*)d_in[11];
    const float* bfc = (const float*)d_in[12];
    const float* W_ih = (const float*)d_in[13];
    const float* W_hh = (const float*)d_in[14];
    const float* b_ih = (const float*)d_in[15];
    const float* b_hh = (const float*)d_in[16];
    const float* Wp1 = (const float*)d_in[17];
    const float* bp1 = (const float*)d_in[18];
    const float* Wp2 = (const float*)d_in[19];
    const float* bp2 = (const float*)d_in[20];
    const float* Wv1 = (const float*)d_in[21];
    const float* bv1 = (const float*)d_in[22];
    const float* Wv2 = (const float*)d_in[23];
    const float* bv2 = (const float*)d_in[24];

    float* out = (float*)d_out;
    float* o_logits = out;           // 5120
    float* o_v = out + 5120;         // 1024
    float* o_hT = out + 6144;        // 8192
    float* o_cT = out + 14336;       // 8192

    const int SMEM1 = 2 * 21168 * 4;    // 169344
    const int SMEM2 = 4 * 12800 * 4;    // 204800
    const int SMEM3 = 8 * 5184 * 4;     // 165888
    const int SMEML = (32768 + 2080 + 1024 + 8) * 4;  // 143520
    cudaFuncSetAttribute(conv1_kernel, cudaFuncAttributeMaxDynamicSharedMemorySize, SMEM1);
    cudaFuncSetAttribute(conv2_kernel, cudaFuncAttributeMaxDynamicSharedMemorySize, SMEM2);
    cudaFuncSetAttribute(conv3_kernel, cudaFuncAttributeMaxDynamicSharedMemorySize, SMEM3);
    cudaFuncSetAttribute(lstm_kernel, cudaFuncAttributeMaxDynamicSharedMemorySize, SMEML);

    prep_kernel<<<2176, 256>>>(W_hh, b_ih, b_hh, Wp1, Wv1, W1, W2, W3, W_ih);
    conv1_kernel<<<512, 640, SMEM1>>>(image, b1);
    conv2_kernel<<<256, 288, SMEM2>>>(b2);
    conv3_kernel<<<128, 448, SMEM3>>>(b3);
    gemm_fc_kernel<<<dim3(512 / 64, 1024 / 64), 128>>>(Wfc, bfc);
    onehot_kernel<<<4, 256>>>(la);
    gemm_pre_kernel<<<dim3(1024 / 64, 1024 / 64), 128>>>();
    lstm_kernel<<<32, 256, SMEML>>>(done, h0, c0, o_hT, o_cT);
    heads_kernel<<<128, 128>>>(bp1, Wp2, bp2, bv1, Wv2, bv2, o_logits, o_v);
}

// round 11
// speedup vs baseline: 1.4636x; 1.4636x over previous
#include <cuda_runtime.h>
#include <math.h>
#include <stdint.h>

// ----------------------------------------------------------------------------
// Problem constants
//   T=32, B=32, TB=1024, NA=5, HID=256, FEAT=512, IN_DIM=517 (pad 544), FLAT=3136
// Output layout (22528 floats): logits[1024*5] | v[1024] | hT[32*256] | cT[32*256]
// ----------------------------------------------------------------------------

#define TBn 1024
#define KPAD 544    // padded IN_DIM for tf32 GEMM (multiple of 32)

// Scratch (device globals; no allocation allowed)
__device__ float g_x1[TBn * 32 * 20 * 20];   // conv1 out
__device__ float g_x2[TBn * 64 * 9 * 9];     // conv2 out
__device__ float g_x3[TBn * 3136];           // conv3 out (flatten, C,H,W)
__device__ float g_xs[TBn * KPAD];           // feat || one-hot || zero pad
__device__ float g_pre[TBn * 1024];          // x @ W_ih^T + b_ih + b_hh
__device__ float g_whhT[256 * 1024];         // W_hh transposed: [k][4*HID]
__device__ float g_wihp[1024 * KPAD];        // W_ih zero-padded to KPAD
__device__ float g_bsum[1024];               // b_ih + b_hh
__device__ float g_wp1T[256 * 64];           // Wp1 transposed [k][64]
__device__ float g_wv1T[256 * 64];           // Wv1 transposed [k][64]
__device__ float g_hs[TBn * 256];            // all h outputs
// Pre-packed conv weights, transposed to [k][oc].
__device__ float g_w1p[192 * 32];            // conv1 W
__device__ float g_w2p[512 * 64];            // conv2 W
__device__ float g_w3p[576 * 64];            // conv3 W

__device__ __forceinline__ float sigmoidf(float x) { return 1.0f / (1.0f + expf(-x)); }

__device__ __forceinline__ unsigned f2tf(float f) {
    unsigned u;
    asm("cvt.rna.tf32.f32 %0, %1;" : "=r"(u) : "f"(f));
    return u;
}

// ---- cluster / DSMEM helpers ----
__device__ __forceinline__ uint32_t smem_u32(const void* p) {
    uint32_t a;
    asm("{ .reg .u64 t; cvta.to.shared.u64 t, %1; cvt.u32.u64 %0, t; }"
        : "=r"(a) : "l"(p));
    return a;
}
__device__ __forceinline__ uint32_t mapa_rank(uint32_t saddr, uint32_t rank) {
    uint32_t r;
    asm("mapa.shared::cluster.u32 %0, %1, %2;" : "=r"(r) : "r"(saddr), "r"(rank));
    return r;
}
__device__ __forceinline__ void st_cluster_f32(uint32_t addr, float v) {
    asm volatile("st.shared::cluster.f32 [%0], %1;" :: "r"(addr), "f"(v) : "memory");
}
#define CLUSTER_SYNC() do { \
    asm volatile("barrier.cluster.arrive.aligned;" ::: "memory"); \
    asm volatile("barrier.cluster.wait.aligned;" ::: "memory"); \
} while (0)

// ----------------------------------------------------------------------------
// prep
// ----------------------------------------------------------------------------
__global__ void prep_kernel(const float* __restrict__ W_hh,
                            const float* __restrict__ b_ih,
                            const float* __restrict__ b_hh,
                            const float* __restrict__ Wp1,
                            const float* __restrict__ Wv1,
                            const float* __restrict__ W1,
                            const float* __restrict__ W2,
                            const float* __restrict__ W3,
                            const float* __restrict__ W_ih) {
    int idx = blockIdx.x * blockDim.x + threadIdx.x;
    if (idx < 262144) {
        int j = idx >> 8, k = idx & 255;
        g_whhT[k * 1024 + j] = W_hh[idx];
    }
    if (idx < 16384) {
        int j = idx >> 8, k = idx & 255;
        g_wp1T[k * 64 + j] = Wp1[idx];
        g_wv1T[k * 64 + j] = Wv1[idx];
    }
    if (idx < 1024) g_bsum[idx] = b_ih[idx] + b_hh[idx];
    if (idx < 6144) {
        int oc = idx / 192, k = idx % 192;
        g_w1p[k * 32 + oc] = W1[idx];
    }
    if (idx < 32768) {
        int oc = idx >> 9, k = idx & 511;
        g_w2p[k * 64 + oc] = W2[idx];
    }
    if (idx < 36864) {
        int oc = idx / 576, k = idx % 576;
        g_w3p[k * 64 + oc] = W3[idx];
    }
    if (idx < 1024 * KPAD) {
        int row = idx / KPAD, col = idx % KPAD;
        g_wihp[idx] = (col < 517) ? W_ih[row * 517 + col] : 0.0f;
    }
}

// ----------------------------------------------------------------------------
// one-hot columns of xs (cols 512..516) + zero pad (517..543)
// ----------------------------------------------------------------------------
__global__ void onehot_kernel(const int* __restrict__ la) {
    int r = blockIdx.x * blockDim.x + threadIdx.x;
    if (r < TBn) {
        int a = la[r];
        float* p = g_xs + r * KPAD + 512;
#pragma unroll
        for (int j = 0; j < 5; j++) p[j] = (j == a) ? 1.0f : 0.0f;
#pragma unroll
        for (int j = 5; j < 32; j++) p[j] = 0.0f;
    }
}

// ----------------------------------------------------------------------------
// conv1: in (TB,3,84,84)/255, W (32,3,8,8) stride4 -> (TB,32,20,20) relu
// 1 image/block, 640 threads: (oy 0-19) x (quarter 0-3) x (oc-group 0-7 of 4).
// Grid 1024 -> per-SM image count 6.92 (fine-grain wave packing).
// ----------------------------------------------------------------------------
__global__ void __launch_bounds__(640, 1)
conv1_kernel(const float* __restrict__ img, const float* __restrict__ b1) {
    extern __shared__ float sm[];            // 21168 floats (one image)
    int tid = threadIdx.x;
    {
        const float4* g4 = reinterpret_cast<const float4*>(img + blockIdx.x * 21168);
        float4* s4 = reinterpret_cast<float4*>(sm);
        for (int i = tid; i < 5292; i += 640) {
            float4 v = g4[i];
            v.x *= (1.0f / 255.0f); v.y *= (1.0f / 255.0f);
            v.z *= (1.0f / 255.0f); v.w *= (1.0f / 255.0f);
            s4[i] = v;
        }
    }
    __syncthreads();

    int oy = tid >> 5, rem = tid & 31;
    int q = rem >> 3, og = rem & 7;          // q: 5-px quarter, og: 4 oc
    const float4* w4 = reinterpret_cast<const float4*>(g_w1p);

    float acc[5][4];
#pragma unroll
    for (int p = 0; p < 5; p++)
#pragma unroll
        for (int c = 0; c < 4; c++) acc[p][c] = 0.0f;

    for (int ic = 0; ic < 3; ic++) {
        for (int ky = 0; ky < 8; ky++) {
            const float* row = sm + ic * 7056 + (oy * 4 + ky) * 84 + q * 20;
            float rr[24];
#pragma unroll
            for (int v = 0; v < 6; v++) {
                float4 t = *reinterpret_cast<const float4*>(row + v * 4);
                rr[v * 4 + 0] = t.x; rr[v * 4 + 1] = t.y;
                rr[v * 4 + 2] = t.z; rr[v * 4 + 3] = t.w;
            }
            int kbase = (ic * 8 + ky) * 8;
#pragma unroll
            for (int kx = 0; kx < 8; kx++) {
                int k = kbase + kx;
                float4 w = __ldg(&w4[k * 8 + og]);
#pragma unroll
                for (int p = 0; p < 5; p++) {
                    float v = rr[p * 4 + kx];
                    acc[p][0] = fmaf(v, w.x, acc[p][0]);
                    acc[p][1] = fmaf(v, w.y, acc[p][1]);
                    acc[p][2] = fmaf(v, w.z, acc[p][2]);
                    acc[p][3] = fmaf(v, w.w, acc[p][3]);
                }
            }
        }
    }
    float* o = g_x1 + blockIdx.x * 12800;
#pragma unroll
    for (int c = 0; c < 4; c++) {
        int oc = og * 4 + c;
        float bb = __ldg(&b1[oc]);
        float* op = o + oc * 400 + oy * 20 + q * 5;
#pragma unroll
        for (int p = 0; p < 5; p++) op[p] = fmaxf(acc[p][c] + bb, 0.0f);
    }
}

// ----------------------------------------------------------------------------
// conv2: (TB,32,20,20) * W(64,32,4,4) s2 -> (TB,64,9,9) relu  (R8 layout)
// ----------------------------------------------------------------------------
__global__ void __launch_bounds__(288, 1)
conv2_kernel(const float* __restrict__ b2) {
    extern __shared__ float sm[];            // 4 * 12800 floats
    int tid = threadIdx.x;
    {
        const float4* g4 = reinterpret_cast<const float4*>(g_x1 + blockIdx.x * 4 * 12800);
        float4* s4 = reinterpret_cast<float4*>(sm);
        for (int i = tid; i < 12800; i += 288) s4[i] = g4[i];
    }
    __syncthreads();

    int im = tid / 72, r = tid % 72;
    int oy = r >> 3, ocg = r & 7;
    const float* ims = sm + im * 12800;
    const float4* w4 = reinterpret_cast<const float4*>(g_w2p);

    float acc[9][8];
#pragma unroll
    for (int p = 0; p < 9; p++)
#pragma unroll
        for (int c = 0; c < 8; c++) acc[p][c] = 0.0f;

    for (int ic = 0; ic < 32; ic++) {
#pragma unroll
        for (int ky = 0; ky < 4; ky++) {
            const float* row = ims + ic * 400 + (oy * 2 + ky) * 20;
            float rr[20];
#pragma unroll
            for (int v = 0; v < 5; v++) {
                float4 t = *reinterpret_cast<const float4*>(row + v * 4);
                rr[v * 4 + 0] = t.x; rr[v * 4 + 1] = t.y;
                rr[v * 4 + 2] = t.z; rr[v * 4 + 3] = t.w;
            }
            int kbase = (ic * 4 + ky) * 4;
#pragma unroll
            for (int kx = 0; kx < 4; kx++) {
                int k = kbase + kx;
                float4 w0 = __ldg(&w4[k * 16 + ocg * 2]);
                float4 w1 = __ldg(&w4[k * 16 + ocg * 2 + 1]);
#pragma unroll
                for (int p = 0; p < 9; p++) {
                    float v = rr[p * 2 + kx];
                    acc[p][0] = fmaf(v, w0.x, acc[p][0]);
                    acc[p][1] = fmaf(v, w0.y, acc[p][1]);
                    acc[p][2] = fmaf(v, w0.z, acc[p][2]);
                    acc[p][3] = fmaf(v, w0.w, acc[p][3]);
                    acc[p][4] = fmaf(v, w1.x, acc[p][4]);
                    acc[p][5] = fmaf(v, w1.y, acc[p][5]);
                    acc[p][6] = fmaf(v, w1.z, acc[p][6]);
                    acc[p][7] = fmaf(v, w1.w, acc[p][7]);
                }
            }
        }
    }
    int n = blockIdx.x * 4 + im;
    float* o = g_x2 + n * 5184;
#pragma unroll
    for (int c = 0; c < 8; c++) {
        int oc = ocg * 8 + c;
        float bb = __ldg(&b2[oc]);
        float* op = o + oc * 81 + oy * 9;
#pragma unroll
        for (int p = 0; p < 9; p++) op[p] = fmaxf(acc[p][c] + bb, 0.0f);
    }
}

// ----------------------------------------------------------------------------
// conv3: (TB,64,9,9) * W(64,64,3,3) s1 -> (TB,64,7,7) relu -> flatten
// Persistent grid 148: block handles images [bid*1024/148,(bid+1)*1024/148)
// (6 or 7), in chunks of <=4 staged to smem. 448 threads = 4 img x 112:
// (oy 0-6) x (oc-half 0-15 of 4 oc). Per-SM work balanced by construction.
// ----------------------------------------------------------------------------
__global__ void __launch_bounds__(448, 1)
conv3_kernel(const float* __restrict__ b3) {
    extern __shared__ float sm[];            // 4 * 5184 floats
    int tid = threadIdx.x;
    int im = tid / 112, r = tid % 112;
    int oy = r >> 4, oh = r & 15;            // oh: 4-oc group
    const float4* w4 = reinterpret_cast<const float4*>(g_w3p);

    int s = (blockIdx.x * 1024) / 148;
    int e = ((blockIdx.x + 1) * 1024) / 148;

    for (int c0 = s; c0 < e; c0 += 4) {
        int cnt = min(4, e - c0);
        // stage cnt images
        {
            const float4* g4 = reinterpret_cast<const float4*>(g_x2 + c0 * 5184);
            float4* s4 = reinterpret_cast<float4*>(sm);
            for (int i = tid; i < cnt * 1296; i += 448) s4[i] = g4[i];
        }
        __syncthreads();

        if (im < cnt) {
            const float* ims = sm + im * 5184;
            float acc[7][4];
#pragma unroll
            for (int p = 0; p < 7; p++)
#pragma unroll
                for (int c = 0; c < 4; c++) acc[p][c] = 0.0f;

            for (int ic = 0; ic < 64; ic++) {
#pragma unroll
                for (int ky = 0; ky < 3; ky++) {
                    const float* row = ims + ic * 81 + (oy + ky) * 9;
                    float rr[9];
#pragma unroll
                    for (int v = 0; v < 9; v++) rr[v] = row[v];
                    int kbase = (ic * 3 + ky) * 3;
#pragma unroll
                    for (int kx = 0; kx < 3; kx++) {
                        int k = kbase + kx;
                        float4 w = __ldg(&w4[k * 16 + oh]);
#pragma unroll
                        for (int p = 0; p < 7; p++) {
                            float v = rr[p + kx];
                            acc[p][0] = fmaf(v, w.x, acc[p][0]);
                            acc[p][1] = fmaf(v, w.y, acc[p][1]);
                            acc[p][2] = fmaf(v, w.z, acc[p][2]);
                            acc[p][3] = fmaf(v, w.w, acc[p][3]);
                        }
                    }
                }
            }
            int n = c0 + im;
            float* o = g_x3 + n * 3136;
#pragma unroll
            for (int c = 0; c < 4; c++) {
                int oc = oh * 4 + c;
                float bb = __ldg(&b3[oc]);
                float* op = o + oc * 49 + oy * 7;
#pragma unroll
                for (int p = 0; p < 7; p++) op[p] = fmaxf(acc[p][c] + bb, 0.0f);
            }
        }
        __syncthreads();
    }
}

// ----------------------------------------------------------------------------
// tf32 tensor-core GEMM: C[M x N] = act(A[M x K] * B[N x K]^T + bias)
// ----------------------------------------------------------------------------
__device__ __forceinline__ void mma_tf32(float* c, const unsigned* a, const unsigned* b) {
    asm volatile(
        "mma.sync.aligned.m16n8k8.row.col.f32.tf32.tf32.f32 "
        "{%0,%1,%2,%3}, {%4,%5,%6,%7}, {%8,%9}, {%0,%1,%2,%3};\n"
        : "+f"(c[0]), "+f"(c[1]), "+f"(c[2]), "+f"(c[3])
        : "r"(a[0]), "r"(a[1]), "r"(a[2]), "r"(a[3]), "r"(b[0]), "r"(b[1]));
}

__device__ __forceinline__ void gemm_tf32(const float* __restrict__ A, int lda,
                                          const float* __restrict__ B, int ldb,
                                          const float* __restrict__ bias,
                                          float* __restrict__ C, int ldc,
                                          int K, bool relu) {
    __shared__ unsigned As[2][64][36];
    __shared__ unsigned Bs[2][64][36];
    int tid = threadIdx.x, lane = tid & 31, warp = tid >> 5;
    int bm = blockIdx.y * 64, bn = blockIdx.x * 64;
    int wm = (warp & 1) << 5, wn = (warp >> 1) << 5;

    float c[2][4][4];
#pragma unroll
    for (int mt = 0; mt < 2; mt++)
#pragma unroll
        for (int nt = 0; nt < 4; nt++)
#pragma unroll
            for (int i = 0; i < 4; i++) c[mt][nt][i] = 0.0f;

    int ntiles = K >> 5;
    float4 pa[4], pb[4];

#pragma unroll
    for (int i = 0; i < 4; i++) {
        int idx = tid + (i << 7);
        int row = idx >> 3, c4 = (idx & 7) << 2;
        pa[i] = *reinterpret_cast<const float4*>(A + (bm + row) * lda + c4);
        pb[i] = *reinterpret_cast<const float4*>(B + (bn + row) * ldb + c4);
    }
#pragma unroll
    for (int i = 0; i < 4; i++) {
        int idx = tid + (i << 7);
        int row = idx >> 3, c4 = (idx & 7) << 2;
        uint4 ta = {f2tf(pa[i].x), f2tf(pa[i].y), f2tf(pa[i].z), f2tf(pa[i].w)};
        uint4 tb = {f2tf(pb[i].x), f2tf(pb[i].y), f2tf(pb[i].z), f2tf(pb[i].w)};
        *reinterpret_cast<uint4*>(&As[0][row][c4]) = ta;
        *reinterpret_cast<uint4*>(&Bs[0][row][c4]) = tb;
    }
    __syncthreads();

    for (int t = 0; t < ntiles; t++) {
        int buf = t & 1;
        if (t + 1 < ntiles) {
            int k0 = (t + 1) << 5;
#pragma unroll
            for (int i = 0; i < 4; i++) {
                int idx = tid + (i << 7);
                int row = idx >> 3, c4 = (idx & 7) << 2;
                pa[i] = *reinterpret_cast<const float4*>(A + (bm + row) * lda + k0 + c4);
                pb[i] = *reinterpret_cast<const float4*>(B + (bn + row) * ldb + k0 + c4);
            }
        }
        int r = lane >> 2, q = lane & 3;
#pragma unroll
        for (int ks = 0; ks < 4; ks++) {
            unsigned a[2][4], b[4][2];
            int kc = ks << 3;
#pragma unroll
            for (int mt = 0; mt < 2; mt++) {
                int mr = wm + (mt << 4) + r;
                a[mt][0] = As[buf][mr][kc + q];
                a[mt][1] = As[buf][mr + 8][kc + q];
                a[mt][2] = As[buf][mr][kc + q + 4];
                a[mt][3] = As[buf][mr + 8][kc + q + 4];
            }
#pragma unroll
            for (int nt = 0; nt < 4; nt++) {
                int nr = wn + (nt << 3) + r;
                b[nt][0] = Bs[buf][nr][kc + q];
                b[nt][1] = Bs[buf][nr][kc + q + 4];
            }
#pragma unroll
            for (int mt = 0; mt < 2; mt++)
#pragma unroll
                for (int nt = 0; nt < 4; nt++)
                    mma_tf32(c[mt][nt], a[mt], b[nt]);
        }
        if (t + 1 < ntiles) {
            int nbuf = buf ^ 1;
#pragma unroll
            for (int i = 0; i < 4; i++) {
                int idx = tid + (i << 7);
                int row = idx >> 3, c4 = (idx & 7) << 2;
                uint4 ta = {f2tf(pa[i].x), f2tf(pa[i].y), f2tf(pa[i].z), f2tf(pa[i].w)};
                uint4 tb = {f2tf(pb[i].x), f2tf(pb[i].y), f2tf(pb[i].z), f2tf(pb[i].w)};
                *reinterpret_cast<uint4*>(&As[nbuf][row][c4]) = ta;
                *reinterpret_cast<uint4*>(&Bs[nbuf][row][c4]) = tb;
            }
            __syncthreads();
        }
    }

#pragma unroll
    for (int mt = 0; mt < 2; mt++) {
#pragma unroll
        for (int nt = 0; nt < 4; nt++) {
            int row = bm + wm + (mt << 4) + (lane >> 2);
            int col = bn + wn + (nt << 3) + ((lane & 3) << 1);
            float b0 = bias[col], b1 = bias[col + 1];
            float v0 = c[mt][nt][0] + b0;
            float v1 = c[mt][nt][1] + b1;
            float v2 = c[mt][nt][2] + b0;
            float v3 = c[mt][nt][3] + b1;
            if (relu) {
                v0 = fmaxf(v0, 0.0f); v1 = fmaxf(v1, 0.0f);
                v2 = fmaxf(v2, 0.0f); v3 = fmaxf(v3, 0.0f);
            }
            C[row * ldc + col] = v0;
            C[row * ldc + col + 1] = v1;
            C[(row + 8) * ldc + col] = v2;
            C[(row + 8) * ldc + col + 1] = v3;
        }
    }
}

__global__ void __launch_bounds__(128)
gemm_fc_kernel(const float* __restrict__ Wfc, const float* __restrict__ bfc) {
    gemm_tf32(g_x3, 3136, Wfc, 3136, bfc, g_xs, KPAD, 3136, true);
}

__global__ void __launch_bounds__(128)
gemm_pre_kernel() {
    gemm_tf32(g_xs, KPAD, g_wihp, KPAD, g_bsum, g_pre, 1024, KPAD, false);
}

// ----------------------------------------------------------------------------
// LSTM: 4 clusters x 8 CTAs, W_hh slice SMEM-resident, DSMEM gate exchange.
// (R8 scalar-FMA version.)
// ----------------------------------------------------------------------------
__global__ void __launch_bounds__(256, 1) __cluster_dims__(8, 1, 1)
lstm_kernel(const float* __restrict__ done,
            const float* __restrict__ h0,
            const float* __restrict__ c0,
            float* __restrict__ hT,
            float* __restrict__ cT) {
    extern __shared__ float sm[];
    float* wsl = sm;                    // 256*128 = 32768 floats (weight slice)
    float* h_s = sm + 32768;            // 8*260 = 2080 floats (padded h, full copy)
    float* gbuf = h_s + 2080;           // 4*8*32 = 1024 floats (owned gate values)
    float* m_s = gbuf + 1024;           // 8 floats (masks)

    int tid = threadIdx.x;
    unsigned rank;
    asm("mov.u32 %0, %%cluster_ctarank;" : "=r"(rank));
    int cl = blockIdx.x >> 3;
    int bbase = cl * 8;

    {
        const float* src = g_whhT + 128 * (int)rank;
        for (int i = tid; i < 8192; i += 256) {
            int k = i >> 5, j4 = (i & 31) << 2;
            *reinterpret_cast<float4*>(&wsl[k * 128 + j4]) =
                *reinterpret_cast<const float4*>(&src[k * 1024 + j4]);
        }
    }
    for (int i = tid; i < 2048; i += 256) {
        int b = i >> 8, k = i & 255;
        h_s[b * 260 + k] = h0[(bbase + b) * 256 + k];
    }
    int ob = tid >> 5, os = tid & 31;
    int ou = 32 * (int)rank + os;
    float c_reg = c0[(bbase + ob) * 256 + ou];
    float hn = 0.0f;

    int b = tid & 7, jg = tid >> 3;
    int jbase = 4 * jg;
    int gt = (int)rank >> 1;
    int ubase = ((128 * (int)rank) & 255) + jbase;
    uint32_t owner = (uint32_t)(ubase >> 5);
    uint32_t gbuf_a = smem_u32(gbuf);
    uint32_t h_a = smem_u32(h_s);
    uint32_t peer_gbuf = mapa_rank(gbuf_a, owner);
    uint32_t goff = (uint32_t)(((gt * 8 + b) * 32 + (ubase & 31)) * 4);
    uint32_t hpeer[8];
#pragma unroll
    for (int p = 0; p < 8; p++) hpeer[p] = mapa_rank(h_a, (uint32_t)p);
    uint32_t hoff = (uint32_t)((ob * 260 + ou) * 4);

    __syncthreads();
    CLUSTER_SYNC();

    for (int t = 0; t < 32; t++) {
        if (tid < 8) m_s[tid] = 1.0f - __ldg(&done[t * 32 + bbase + tid]);
        __syncthreads();
        for (int i = tid; i < 2048; i += 256) {
            int bb = i >> 8, k = i & 255;
            h_s[bb * 260 + k] *= m_s[bb];
        }
        c_reg *= m_s[ob];
        __syncthreads();

        int row = (t << 5) + bbase + b;
        float4 a = *reinterpret_cast<const float4*>(
            g_pre + row * 1024 + 128 * (int)rank + jbase);
        float acc0 = a.x, acc1 = a.y, acc2 = a.z, acc3 = a.w;
        const float* hb = h_s + b * 260;
#pragma unroll 8
        for (int k = 0; k < 256; k++) {
            float hv = hb[k];
            float4 w = *reinterpret_cast<const float4*>(&wsl[k * 128 + jbase]);
            acc0 = fmaf(hv, w.x, acc0);
            acc1 = fmaf(hv, w.y, acc1);
            acc2 = fmaf(hv, w.z, acc2);
            acc3 = fmaf(hv, w.w, acc3);
        }
        st_cluster_f32(peer_gbuf + goff, acc0);
        st_cluster_f32(peer_gbuf + goff + 4, acc1);
        st_cluster_f32(peer_gbuf + goff + 8, acc2);
        st_cluster_f32(peer_gbuf + goff + 12, acc3);
        CLUSTER_SYNC();

        {
            float gi = sigmoidf(gbuf[(0 * 8 + ob) * 32 + os]);
            float gf = sigmoidf(gbuf[(1 * 8 + ob) * 32 + os]);
            float gg = tanhf(gbuf[(2 * 8 + ob) * 32 + os]);
            float go = sigmoidf(gbuf[(3 * 8 + ob) * 32 + os]);
            c_reg = gf * c_reg + gi * gg;
            hn = go * tanhf(c_reg);
            g_hs[((t << 5) + bbase + ob) * 256 + ou] = hn;
#pragma unroll
            for (int p = 0; p < 8; p++) st_cluster_f32(hpeer[p] + hoff, hn);
        }
        CLUSTER_SYNC();
    }
    hT[(bbase + ob) * 256 + ou] = hn;
    cT[(bbase + ob) * 256 + ou] = c_reg;
}

// ----------------------------------------------------------------------------
// Heads: 8 rows per block; weights loaded once per k, 8 FMAs each.
// ----------------------------------------------------------------------------
__global__ void __launch_bounds__(128)
heads_kernel(const float* __restrict__ bp1,
             const float* __restrict__ Wp2,
             const float* __restrict__ bp2,
             const float* __restrict__ bv1,
             const float* __restrict__ Wv2,
             const float* __restrict__ bv2,
             float* __restrict__ logits,
             float* __restrict__ vout) {
    __shared__ float h_s[8][256];
    __shared__ float hp[8][64];
    __shared__ float hv[8][64];
    int r0 = blockIdx.x * 8, t = threadIdx.x;
    {
        const float4* g4 = reinterpret_cast<const float4*>(g_hs + r0 * 256);
        float4* s4 = reinterpret_cast<float4*>(&h_s[0][0]);
        for (int i = t; i < 512; i += 128) s4[i] = g4[i];
    }
    __syncthreads();

    if (t < 64) {
        float s[8];
#pragma unroll
        for (int r = 0; r < 8; r++) s[r] = bp1[t];
#pragma unroll 4
        for (int k = 0; k < 256; k++) {
            float w = __ldg(&g_wp1T[k * 64 + t]);
#pragma unroll
            for (int r = 0; r < 8; r++) s[r] = fmaf(h_s[r][k], w, s[r]);
        }
#pragma unroll
        for (int r = 0; r < 8; r++) hp[r][t] = tanhf(s[r]);
    } else {
        int j = t - 64;
        float s[8];
#pragma unroll
        for (int r = 0; r < 8; r++) s[r] = bv1[j];
#pragma unroll 4
        for (int k = 0; k < 256; k++) {
            float w = __ldg(&g_wv1T[k * 64 + j]);
#pragma unroll
            for (int r = 0; r < 8; r++) s[r] = fmaf(h_s[r][k], w, s[r]);
        }
#pragma unroll
        for (int r = 0; r < 8; r++) hv[r][j] = tanhf(s[r]);
    }
    __syncthreads();

    if (t < 40) {
        int r = t / 5, a = t % 5;
        float s = bp2[a];
#pragma unroll
        for (int k = 0; k < 64; k++) s = fmaf(hp[r][k], Wp2[a * 64 + k], s);
        logits[(r0 + r) * 5 + a] = s;
    }
    if (t >= 64 && t < 72) {
        int r = t - 64;
        float s = bv2[0];
#pragma unroll
        for (int k = 0; k < 64; k++) s = fmaf(hv[r][k], Wv2[k], s);
        vout[r0 + r] = s;
    }
}

// ----------------------------------------------------------------------------
// Launch
// ----------------------------------------------------------------------------
extern "C" void kernel_launch(void* const* d_in, const int* in_sizes, int n_in,
                              void* d_out, int out_size) {
    const float* image = (const float*)d_in[0];
    const int* la = (const int*)d_in[1];
    const float* done = (const float*)d_in[2];
    const float* h0 = (const float*)d_in[3];
    const float* c0 = (const float*)d_in[4];
    const float* W1 = (const float*)d_in[5];
    const float* b1 = (const float*)d_in[6];
    const float* W2 = (const float*)d_in[7];
    const float* b2 = (const float*)d_in[8];
    const float* W3 = (const float*)d_in[9];
    const float* b3 = (const float*)d_in[10];
    const float* Wfc = (const float*)d_in[11];
    const float* bfc = (const float*)d_in[12];
    const float* W_ih = (const float*)d_in[13];
    const float* W_hh = (const float*)d_in[14];
    const float* b_ih = (const float*)d_in[15];
    const float* b_hh = (const float*)d_in[16];
    const float* Wp1 = (const float*)d_in[17];
    const float* bp1 = (const float*)d_in[18];
    const float* Wp2 = (const float*)d_in[19];
    const float* bp2 = (const float*)d_in[20];
    const float* Wv1 = (const float*)d_in[21];
    const float* bv1 = (const float*)d_in[22];
    const float* Wv2 = (const float*)d_in[23];
    const float* bv2 = (const float*)d_in[24];

    float* out = (float*)d_out;
    float* o_logits = out;           // 5120
    float* o_v = out + 5120;         // 1024
    float* o_hT = out + 6144;        // 8192
    float* o_cT = out + 14336;       // 8192

    const int SMEM1 = 21168 * 4;        // 84672 (1 image)
    const int SMEM2 = 4 * 12800 * 4;    // 204800
    const int SMEM3 = 4 * 5184 * 4;     // 82944 (4-image chunk)
    const int SMEML = (32768 + 2080 + 1024 + 8) * 4;  // 143520
    cudaFuncSetAttribute(conv1_kernel, cudaFuncAttributeMaxDynamicSharedMemorySize, SMEM1);
    cudaFuncSetAttribute(conv2_kernel, cudaFuncAttributeMaxDynamicSharedMemorySize, SMEM2);
    cudaFuncSetAttribute(conv3_kernel, cudaFuncAttributeMaxDynamicSharedMemorySize, SMEM3);
    cudaFuncSetAttribute(lstm_kernel, cudaFuncAttributeMaxDynamicSharedMemorySize, SMEML);

    prep_kernel<<<2176, 256>>>(W_hh, b_ih, b_hh, Wp1, Wv1, W1, W2, W3, W_ih);
    conv1_kernel<<<1024, 640, SMEM1>>>(image, b1);
    conv2_kernel<<<256, 288, SMEM2>>>(b2);
    conv3_kernel<<<148, 448, SMEM3>>>(b3);
    gemm_fc_kernel<<<dim3(512 / 64, 1024 / 64), 128>>>(Wfc, bfc);
    onehot_kernel<<<4, 256>>>(la);
    gemm_pre_kernel<<<dim3(1024 / 64, 1024 / 64), 128>>>();
    lstm_kernel<<<32, 256, SMEML>>>(done, h0, c0, o_hT, o_cT);
    heads_kernel<<<128, 128>>>(bp1, Wp2, bp2, bv1, Wv2, bv2, o_logits, o_v);
}